// round 13
// baseline (speedup 1.0000x reference)
#include <cuda_runtime.h>
#include <math.h>

#define Bz 8
#define Cc 64
#define Nn 32768
#define Rr 32
#define R3v (Rr*Rr*Rr)

// ---------------- device scratch (no allocations allowed) ----------------
__device__ __align__(16) float g_acc[(size_t)Bz*R3v*Cc];   // voxel accum -> vox (in place)
__device__ __align__(16) float g_cnt[Bz*R3v];
__device__ __align__(16) float g_c1 [(size_t)Bz*R3v*Cc];   // conv1 out (channels-last)
__device__ __align__(16) float g_c2 [(size_t)Bz*R3v*Cc];   // conv2 out (channels-last)
__device__ __align__(16) float g_featT[(size_t)Bz*Nn*Cc];  // features transposed [b][n][c]
__device__ __align__(16) float g_w1T[27*64*64];            // [tap][ci][co]
__device__ __align__(16) float g_w2T[27*64*64];
__device__ __align__(16) float g_mlpT[64*64];              // [c][o]
__device__ float g_s1[64], g_b1[64], g_s2[64], g_b2[64], g_sp[64], g_bp[64];
__device__ float g_mean[Bz*4];
__device__ float g_scl[Bz];

// ---------------- f32x2 helpers (FFMA2: 2x fp32 FMA throughput) ----------
__device__ __forceinline__ unsigned long long pack2(float x, float y) {
    unsigned long long r;
    asm("mov.b64 %0, {%1, %2};" : "=l"(r) : "f"(x), "f"(y));
    return r;
}
__device__ __forceinline__ void fma2(unsigned long long& d, unsigned long long a, unsigned long long b) {
    asm("fma.rn.f32x2 %0, %1, %2, %0;" : "+l"(d) : "l"(a), "l"(b));
}
__device__ __forceinline__ float2 unpack2(unsigned long long v) {
    float2 r;
    asm("mov.b64 {%0, %1}, %2;" : "=f"(r.x), "=f"(r.y) : "l"(v));
    return r;
}

// ---------------- prep: fold BN into scale/bias, transpose mlp ----------
__global__ void prep_params(
    const float* __restrict__ conv1_b, const float* __restrict__ bn1_g, const float* __restrict__ bn1_b,
    const float* __restrict__ bn1_m,  const float* __restrict__ bn1_v,
    const float* __restrict__ conv2_b, const float* __restrict__ bn2_g, const float* __restrict__ bn2_b,
    const float* __restrict__ bn2_m,  const float* __restrict__ bn2_v,
    const float* __restrict__ mlp_w,  const float* __restrict__ mlp_b,
    const float* __restrict__ bnp_g,  const float* __restrict__ bnp_b,
    const float* __restrict__ bnp_m,  const float* __restrict__ bnp_v)
{
    int c = threadIdx.x;
    if (c < 64) {
        float s1 = bn1_g[c] * rsqrtf(bn1_v[c] + 1e-4f);
        g_s1[c] = s1;  g_b1[c] = (conv1_b[c] - bn1_m[c]) * s1 + bn1_b[c];
        float s2 = bn2_g[c] * rsqrtf(bn2_v[c] + 1e-4f);
        g_s2[c] = s2;  g_b2[c] = (conv2_b[c] - bn2_m[c]) * s2 + bn2_b[c];
        float sp = bnp_g[c] * rsqrtf(bnp_v[c] + 1e-4f);
        g_sp[c] = sp;  g_bp[c] = (mlp_b[c] - bnp_m[c]) * sp + bnp_b[c];
        for (int o = 0; o < 64; ++o) g_mlpT[c*64 + o] = mlp_w[o*64 + c];
    }
}

// ---------------- weight transpose [co][ci][27] -> [t][ci][co] -----------
__global__ void transpose_w(const float* __restrict__ w1, const float* __restrict__ w2)
{
    int e = blockIdx.x * 256 + threadIdx.x;
    if (e < 110592) {
        int co = e & 63, ci = (e >> 6) & 63, t = e >> 12;
        g_w1T[e] = w1[(co*64 + ci)*27 + t];
    } else if (e < 221184) {
        int o = e - 110592;
        int co = o & 63, ci = (o >> 6) & 63, t = o >> 12;
        g_w2T[o] = w2[(co*64 + ci)*27 + t];
    }
}

// ---------------- features [b][c][n] -> [b][n][c] ------------------------
__global__ void transpose_feat(const float* __restrict__ feat)
{
    __shared__ float t[32][33];
    int n0 = blockIdx.x * 32, c0 = blockIdx.y * 32, b = blockIdx.z;
    int tx = threadIdx.x, ty = threadIdx.y;
#pragma unroll
    for (int j = 0; j < 32; j += 8)
        t[ty + j][tx] = feat[((size_t)b*64 + c0 + ty + j)*Nn + n0 + tx];
    __syncthreads();
#pragma unroll
    for (int j = 0; j < 32; j += 8)
        g_featT[((size_t)b*Nn + n0 + ty + j)*64 + c0 + tx] = t[tx][ty + j];
}

// ---------------- per-batch mean + max-norm ------------------------------
__global__ void reduce_coords(const float* __restrict__ coords)
{
    __shared__ float sm[1024];
    int b = blockIdx.x, tid = threadIdx.x;
    const float* px = coords + (size_t)b*3*Nn;
    const float* py = px + Nn;
    const float* pz = py + Nn;
    float sx = 0.f, sy = 0.f, sz = 0.f;
    for (int i = tid; i < Nn; i += 1024) { sx += px[i]; sy += py[i]; sz += pz[i]; }

    sm[tid] = sx; __syncthreads();
    for (int s = 512; s > 0; s >>= 1) { if (tid < s) sm[tid] += sm[tid + s]; __syncthreads(); }
    float mx = sm[0] * (1.f / Nn); __syncthreads();

    sm[tid] = sy; __syncthreads();
    for (int s = 512; s > 0; s >>= 1) { if (tid < s) sm[tid] += sm[tid + s]; __syncthreads(); }
    float my = sm[0] * (1.f / Nn); __syncthreads();

    sm[tid] = sz; __syncthreads();
    for (int s = 512; s > 0; s >>= 1) { if (tid < s) sm[tid] += sm[tid + s]; __syncthreads(); }
    float mz = sm[0] * (1.f / Nn); __syncthreads();

    float mm = 0.f;
    for (int i = tid; i < Nn; i += 1024) {
        float dx = px[i] - mx, dy = py[i] - my, dz = pz[i] - mz;
        mm = fmaxf(mm, dx*dx + dy*dy + dz*dz);
    }
    sm[tid] = mm; __syncthreads();
    for (int s = 512; s > 0; s >>= 1) { if (tid < s) sm[tid] = fmaxf(sm[tid], sm[tid + s]); __syncthreads(); }
    if (tid == 0) {
        g_mean[b*4 + 0] = mx; g_mean[b*4 + 1] = my; g_mean[b*4 + 2] = mz;
        g_scl[b] = (float)Rr / (2.f * sqrtf(sm[0]) * (1.f + 1e-6f));
    }
}

// ---------------- zero acc + cnt -----------------------------------------
__global__ void zero_kernel()
{
    int i = blockIdx.x * 256 + threadIdx.x;       // 16384*256 = 4194304
    float4 z = make_float4(0.f, 0.f, 0.f, 0.f);
    reinterpret_cast<float4*>(g_acc)[i] = z;      // Bz*R3v*16 = 4194304 exactly
    if (i < Bz*R3v/4) reinterpret_cast<float4*>(g_cnt)[i] = z;
}

// ---------------- trilinear scatter (warp per point) ----------------------
__global__ __launch_bounds__(256)
void scatter_kernel(const float* __restrict__ coords)
{
    int tid = threadIdx.x;
    int warp = tid >> 5, lane = tid & 31;
    int pid = blockIdx.x * 8 + warp;
    int b = pid >> 15, n = pid & (Nn - 1);

    float mx = g_mean[b*4+0], my = g_mean[b*4+1], mz = g_mean[b*4+2];
    float s  = g_scl[b];
    float cx = coords[((size_t)b*3 + 0)*Nn + n];
    float cy = coords[((size_t)b*3 + 1)*Nn + n];
    float cz = coords[((size_t)b*3 + 2)*Nn + n];
    float vx = fminf(fmaxf((cx - mx)*s + 16.f, 0.f), 31.f);
    float vy = fminf(fmaxf((cy - my)*s + 16.f, 0.f), 31.f);
    float vz = fminf(fmaxf((cz - mz)*s + 16.f, 0.f), 31.f);
    float fx = floorf(vx), fy = floorf(vy), fz = floorf(vz);
    int ix = (int)fx, iy = (int)fy, iz = (int)fz;
    float frx = vx - fx, fry = vy - fy, frz = vz - fz;

    float f0 = g_featT[(size_t)pid*64 + lane];
    float f1 = g_featT[(size_t)pid*64 + 32 + lane];

#pragma unroll
    for (int k = 0; k < 8; ++k) {
        int dx = k >> 2, dy = (k >> 1) & 1, dz = k & 1;
        int xi = min(ix + dx, 31), yi = min(iy + dy, 31), zi = min(iz + dz, 31);
        float w = (dx ? frx : 1.f - frx) * (dy ? fry : 1.f - fry) * (dz ? frz : 1.f - frz);
        size_t vb = (size_t)b*R3v + ((xi*32 + yi)*32 + zi);
        float* ap = g_acc + vb*64;
        atomicAdd(ap + lane,      w * f0);
        atomicAdd(ap + lane + 32, w * f1);
        if (lane == 0) atomicAdd(&g_cnt[vb], w);
    }
}

// ---------------- vox = acc / max(cnt, 1e-8) (in place) -------------------
__global__ void normalize_kernel()
{
    int i = blockIdx.x * 256 + threadIdx.x;   // 4194304 float4
    int v = i >> 4;
    float c = g_cnt[v];
    float r = 1.f / fmaxf(c, 1e-8f);
    float4 f = reinterpret_cast<float4*>(g_acc)[i];
    f.x *= r; f.y *= r; f.z *= r; f.w *= r;
    reinterpret_cast<float4*>(g_acc)[i] = f;
}

// ---------------- 3x3x3 conv + BN + LeakyReLU (channels-last) -------------
// Block: (b, x, y-slab of 8) -> 8y * 32z voxels x 64 co. Thread: 8 vox x 8 co,
// f32x2 packed accumulators -> FFMA2-pipe-bound.
__global__ __launch_bounds__(256, 2)
void conv3d_kernel(const float* __restrict__ in, float* __restrict__ out,
                   const float* __restrict__ wT,
                   const float* __restrict__ sc, const float* __restrict__ bi)
{
    __shared__ __align__(16) float s_in[3*10*34*4];   // [dx][y:10][z:34][ci:4]
    __shared__ __align__(16) float s_w [27*4*64];     // [t][ci][co]

    const int tid = threadIdx.x;
    const int b = blockIdx.z, x = blockIdx.y, y0 = blockIdx.x * 8;
    const int vg = tid >> 3;     // z = vg (0..31)
    const int cg = tid & 7;      // co = p*16 + cg*2 + {0,1}

    unsigned long long acc[8][4];
#pragma unroll
    for (int k = 0; k < 8; ++k)
#pragma unroll
        for (int p = 0; p < 4; ++p) acc[k][p] = 0ull;

    for (int ch = 0; ch < 16; ++ch) {        // ci chunks of 4
        __syncthreads();
#pragma unroll 1
        for (int e = tid; e < 3*10*34*4; e += 256) {
            int ci = e & 3;
            int zi = (e >> 2) % 34;
            int r  = (e >> 2) / 34;
            int yy = r % 10;
            int dx = r / 10;
            int xg = x + dx - 1, yg = y0 + yy - 1, zg = zi - 1;
            float v = 0.f;
            if ((unsigned)xg < 32u && (unsigned)yg < 32u && (unsigned)zg < 32u)
                v = in[((((size_t)b*32 + xg)*32 + yg)*32 + zg)*64 + (ch << 2) + ci];
            s_in[e] = v;
        }
#pragma unroll 1
        for (int e = tid; e < 27*4*64; e += 256) {
            int co = e & 63;
            int ci = (e >> 6) & 3;
            int t  = e >> 8;
            s_w[e] = wT[((size_t)(t*64 + (ch << 2) + ci))*64 + co];
        }
        __syncthreads();
#pragma unroll 1
        for (int t = 0; t < 27; ++t) {
            int dx = t / 9; int rr = t - dx*9; int dy = rr / 3; int dz = rr - dy*3;
            const float* ib = s_in + ((dx*10 + dy)*34 + vg + dz)*4;
            const float* wb = s_w + t*256 + (cg << 1);
#pragma unroll
            for (int ci = 0; ci < 4; ++ci) {
                unsigned long long w0 = *(const unsigned long long*)(wb + ci*64);
                unsigned long long w1 = *(const unsigned long long*)(wb + ci*64 + 16);
                unsigned long long w2 = *(const unsigned long long*)(wb + ci*64 + 32);
                unsigned long long w3 = *(const unsigned long long*)(wb + ci*64 + 48);
#pragma unroll
                for (int k = 0; k < 8; ++k) {
                    float a = ib[k*136 + ci];       // y step = 34*4 floats
                    unsigned long long a2 = pack2(a, a);
                    fma2(acc[k][0], a2, w0);
                    fma2(acc[k][1], a2, w1);
                    fma2(acc[k][2], a2, w2);
                    fma2(acc[k][3], a2, w3);
                }
            }
        }
    }
    // epilogue: BN fold + LeakyReLU(0.1), coalesced float2 stores
#pragma unroll
    for (int k = 0; k < 8; ++k) {
        size_t base = ((((size_t)b*32 + x)*32 + (y0 + k))*32 + vg)*64;
#pragma unroll
        for (int p = 0; p < 4; ++p) {
            int co = p*16 + (cg << 1);
            float2 v = unpack2(acc[k][p]);
            float r0 = v.x * sc[co]     + bi[co];
            float r1 = v.y * sc[co + 1] + bi[co + 1];
            r0 = r0 > 0.f ? r0 : 0.1f * r0;
            r1 = r1 > 0.f ? r1 : 0.1f * r1;
            *reinterpret_cast<float2*>(out + base + co) = make_float2(r0, r1);
        }
    }
}

// ---------------- devoxelize + point-MLP branch + output -------------------
__global__ __launch_bounds__(256)
void devox_kernel(const float* __restrict__ coords, float* __restrict__ out)
{
    __shared__ float s_mlpT[64*64];
    __shared__ float s_out[64][9];
    int tid = threadIdx.x;
#pragma unroll 1
    for (int e = tid; e < 4096; e += 256) s_mlpT[e] = g_mlpT[e];

    int warp = tid >> 5, lane = tid & 31;
    int pid0 = blockIdx.x * 8;
    int pid = pid0 + warp;
    int b = pid >> 15, n = pid & (Nn - 1);
    __syncthreads();

    float mx = g_mean[b*4+0], my = g_mean[b*4+1], mz = g_mean[b*4+2];
    float s  = g_scl[b];
    float cx = coords[((size_t)b*3 + 0)*Nn + n];
    float cy = coords[((size_t)b*3 + 1)*Nn + n];
    float cz = coords[((size_t)b*3 + 2)*Nn + n];
    float vx = fminf(fmaxf((cx - mx)*s + 16.f, 0.f), 31.f);
    float vy = fminf(fmaxf((cy - my)*s + 16.f, 0.f), 31.f);
    float vz = fminf(fmaxf((cz - mz)*s + 16.f, 0.f), 31.f);
    float fx = floorf(vx), fy = floorf(vy), fz = floorf(vz);
    int ix = (int)fx, iy = (int)fy, iz = (int)fz;
    float frx = vx - fx, fry = vy - fy, frz = vz - fz;

    // point branch: p[o] = relu(dot(mlp_w[o,:], feat) * sp + bp)
    float f0 = g_featT[(size_t)pid*64 + lane];
    float f1 = g_featT[(size_t)pid*64 + 32 + lane];
    float p0 = 0.f, p1 = 0.f;
#pragma unroll 1
    for (int c = 0; c < 64; ++c) {
        float fc = __shfl_sync(0xffffffffu, (c < 32) ? f0 : f1, c & 31);
        p0 = fmaf(s_mlpT[c*64 + lane],      fc, p0);
        p1 = fmaf(s_mlpT[c*64 + 32 + lane], fc, p1);
    }

    float d0 = 0.f, d1 = 0.f;
#pragma unroll
    for (int k = 0; k < 8; ++k) {
        int dx = k >> 2, dy = (k >> 1) & 1, dz = k & 1;
        int xi = min(ix + dx, 31), yi = min(iy + dy, 31), zi = min(iz + dz, 31);
        float w = (dx ? frx : 1.f - frx) * (dy ? fry : 1.f - fry) * (dz ? frz : 1.f - frz);
        const float* gp = g_c2 + ((size_t)b*R3v + ((xi*32 + yi)*32 + zi))*64;
        d0 = fmaf(w, gp[lane],      d0);
        d1 = fmaf(w, gp[lane + 32], d1);
    }
    p0 = fmaxf(fmaf(p0, g_sp[lane],      g_bp[lane]),      0.f);
    p1 = fmaxf(fmaf(p1, g_sp[lane + 32], g_bp[lane + 32]), 0.f);
    s_out[lane][warp]      = d0 + p0;
    s_out[lane + 32][warp] = d1 + p1;
    __syncthreads();

    int bb = pid0 >> 15;
    int n0 = pid0 & (Nn - 1);
#pragma unroll
    for (int e = tid; e < 512; e += 256) {
        int o = e >> 3, pi = e & 7;
        out[((size_t)bb*64 + o)*Nn + n0 + pi] = s_out[o][pi];
    }
}

// ---------------- launch ---------------------------------------------------
extern "C" void kernel_launch(void* const* d_in, const int* in_sizes, int n_in,
                              void* d_out, int out_size)
{
    const float* features = (const float*)d_in[0];
    const float* coords   = (const float*)d_in[1];
    const float* conv1_w  = (const float*)d_in[2];
    const float* conv1_b  = (const float*)d_in[3];
    const float* bn1_g    = (const float*)d_in[4];
    const float* bn1_b    = (const float*)d_in[5];
    const float* bn1_m    = (const float*)d_in[6];
    const float* bn1_v    = (const float*)d_in[7];
    const float* conv2_w  = (const float*)d_in[8];
    const float* conv2_b  = (const float*)d_in[9];
    const float* bn2_g    = (const float*)d_in[10];
    const float* bn2_b    = (const float*)d_in[11];
    const float* bn2_m    = (const float*)d_in[12];
    const float* bn2_v    = (const float*)d_in[13];
    const float* mlp_w    = (const float*)d_in[14];
    const float* mlp_b    = (const float*)d_in[15];
    const float* bnp_g    = (const float*)d_in[16];
    const float* bnp_b    = (const float*)d_in[17];
    const float* bnp_m    = (const float*)d_in[18];
    const float* bnp_v    = (const float*)d_in[19];
    float* out = (float*)d_out;

    void *p_acc, *p_c1, *p_c2, *p_w1T, *p_w2T, *p_s1, *p_b1, *p_s2, *p_b2;
    cudaGetSymbolAddress(&p_acc, g_acc);
    cudaGetSymbolAddress(&p_c1,  g_c1);
    cudaGetSymbolAddress(&p_c2,  g_c2);
    cudaGetSymbolAddress(&p_w1T, g_w1T);
    cudaGetSymbolAddress(&p_w2T, g_w2T);
    cudaGetSymbolAddress(&p_s1,  g_s1);
    cudaGetSymbolAddress(&p_b1,  g_b1);
    cudaGetSymbolAddress(&p_s2,  g_s2);
    cudaGetSymbolAddress(&p_b2,  g_b2);

    prep_params<<<1, 64>>>(conv1_b, bn1_g, bn1_b, bn1_m, bn1_v,
                           conv2_b, bn2_g, bn2_b, bn2_m, bn2_v,
                           mlp_w, mlp_b, bnp_g, bnp_b, bnp_m, bnp_v);
    transpose_w<<<864, 256>>>(conv1_w, conv2_w);
    transpose_feat<<<dim3(Nn/32, 2, Bz), dim3(32, 8)>>>(features);
    reduce_coords<<<Bz, 1024>>>(coords);
    zero_kernel<<<16384, 256>>>();
    scatter_kernel<<<(Bz*Nn)/8, 256>>>(coords);
    normalize_kernel<<<16384, 256>>>();
    conv3d_kernel<<<dim3(4, 32, Bz), 256>>>((const float*)p_acc, (float*)p_c1,
                                            (const float*)p_w1T, (const float*)p_s1, (const float*)p_b1);
    conv3d_kernel<<<dim3(4, 32, Bz), 256>>>((const float*)p_c1, (float*)p_c2,
                                            (const float*)p_w2T, (const float*)p_s2, (const float*)p_b2);
    devox_kernel<<<(Bz*Nn)/8, 256>>>(coords, out);
    cudaMemcpyAsync(out + (size_t)Bz*64*Nn, coords,
                    (size_t)Bz*3*Nn*sizeof(float), cudaMemcpyDeviceToDevice);
}

// round 16
// speedup vs baseline: 1.7677x; 1.7677x over previous
#include <cuda_runtime.h>
#include <cuda_bf16.h>
#include <math.h>
#include <stdint.h>

#define Bz 8
#define Nn 32768
#define Rr 32
#define R3v (Rr*Rr*Rr)
#define RP 34
#define RP3 (RP*RP*RP)   // 39304 padded rows per batch

// ---------------- device scratch (no allocations allowed) ----------------
__device__ __align__(16) float g_accp[(size_t)Bz*RP3*64];  // padded voxel accum fp32
__device__ __align__(16) float g_cnt[Bz*RP3];
__device__ __align__(16) float g_c2 [(size_t)Bz*R3v*64];   // conv2 out fp32 (channels-last)
__device__ __align__(16) float g_featT[(size_t)Bz*Nn*64];  // features [b][n][c]
__device__ __align__(16) __nv_bfloat16 g_vhi[(size_t)Bz*RP3*64];  // conv1 input hi
__device__ __align__(16) __nv_bfloat16 g_vlo[(size_t)Bz*RP3*64];  // conv1 input lo
__device__ __align__(16) __nv_bfloat16 g_1hi[(size_t)Bz*RP3*64];  // conv2 input hi
__device__ __align__(16) __nv_bfloat16 g_1lo[(size_t)Bz*RP3*64];  // conv2 input lo
__device__ __align__(16) __nv_bfloat16 g_w1hi[27*64*64], g_w1lo[27*64*64]; // [t][co][ci]
__device__ __align__(16) __nv_bfloat16 g_w2hi[27*64*64], g_w2lo[27*64*64];
__device__ __align__(16) float g_mlpT[64*64];              // [c][o]
__device__ float g_s1[64], g_b1[64], g_s2[64], g_b2[64], g_sp[64], g_bp[64];
__device__ float g_mean[Bz*4];
__device__ float g_scl[Bz];

// ---------------- PTX helpers ---------------------------------------------
static __device__ __forceinline__ uint32_t smem_u32(const void* p) {
    uint32_t a;
    asm("{ .reg .u64 t; cvta.to.shared.u64 t, %1; cvt.u32.u64 %0, t; }" : "=r"(a) : "l"(p));
    return a;
}
#define SWZ(o) ((o) ^ (((o) >> 3) & 0x70))
__device__ __forceinline__ void cp_async16(uint32_t dst, const void* src) {
    asm volatile("cp.async.cg.shared.global [%0], [%1], 16;" :: "r"(dst), "l"(src));
}
__device__ __forceinline__ void ldsm4(uint32_t* r, uint32_t addr) {
    asm volatile("ldmatrix.sync.aligned.m8n8.x4.shared.b16 {%0,%1,%2,%3}, [%4];"
        : "=r"(r[0]), "=r"(r[1]), "=r"(r[2]), "=r"(r[3]) : "r"(addr));
}
__device__ __forceinline__ void mma16816(float* d, const uint32_t* a, uint32_t b0, uint32_t b1) {
    asm volatile("mma.sync.aligned.m16n8k16.row.col.f32.bf16.bf16.f32 "
        "{%0,%1,%2,%3}, {%4,%5,%6,%7}, {%8,%9}, {%0,%1,%2,%3};"
        : "+f"(d[0]), "+f"(d[1]), "+f"(d[2]), "+f"(d[3])
        : "r"(a[0]), "r"(a[1]), "r"(a[2]), "r"(a[3]), "r"(b0), "r"(b1));
}
__device__ __forceinline__ uint32_t bfpack(float lo, float hi) {
    uint32_t r;
    asm("cvt.rn.bf16x2.f32 %0, %1, %2;" : "=r"(r) : "f"(hi), "f"(lo));
    return r;
}

// ---------------- prep: fold BN into scale/bias, transpose mlp -----------
__global__ void prep_params(
    const float* __restrict__ conv1_b, const float* __restrict__ bn1_g, const float* __restrict__ bn1_b,
    const float* __restrict__ bn1_m,  const float* __restrict__ bn1_v,
    const float* __restrict__ conv2_b, const float* __restrict__ bn2_g, const float* __restrict__ bn2_b,
    const float* __restrict__ bn2_m,  const float* __restrict__ bn2_v,
    const float* __restrict__ mlp_w,  const float* __restrict__ mlp_b,
    const float* __restrict__ bnp_g,  const float* __restrict__ bnp_b,
    const float* __restrict__ bnp_m,  const float* __restrict__ bnp_v)
{
    int c = threadIdx.x;
    if (c < 64) {
        float s1 = bn1_g[c] * rsqrtf(bn1_v[c] + 1e-4f);
        g_s1[c] = s1;  g_b1[c] = (conv1_b[c] - bn1_m[c]) * s1 + bn1_b[c];
        float s2 = bn2_g[c] * rsqrtf(bn2_v[c] + 1e-4f);
        g_s2[c] = s2;  g_b2[c] = (conv2_b[c] - bn2_m[c]) * s2 + bn2_b[c];
        float sp = bnp_g[c] * rsqrtf(bnp_v[c] + 1e-4f);
        g_sp[c] = sp;  g_bp[c] = (mlp_b[c] - bnp_m[c]) * sp + bnp_b[c];
        for (int o = 0; o < 64; ++o) g_mlpT[c*64 + o] = mlp_w[o*64 + c];
    }
}

// ---------------- weights [co][ci][27] -> bf16 hi/lo [t][co][ci] ----------
__global__ void prep_weights(const float* __restrict__ w1, const float* __restrict__ w2)
{
    int e = blockIdx.x * 256 + threadIdx.x;   // 221184 total
    const float* src = (e < 110592) ? w1 : w2;
    int o = (e < 110592) ? e : e - 110592;
    int ci = o & 63, co = (o >> 6) & 63, t = o >> 12;
    float v = src[(co*64 + ci)*27 + t];
    __nv_bfloat16 h = __float2bfloat16_rn(v);
    __nv_bfloat16 l = __float2bfloat16_rn(v - __bfloat162float(h));
    int dst = t*4096 + co*64 + ci;
    if (e < 110592) { g_w1hi[dst] = h; g_w1lo[dst] = l; }
    else            { g_w2hi[dst] = h; g_w2lo[dst] = l; }
}

// ---------------- features [b][c][n] -> [b][n][c] ------------------------
__global__ void transpose_feat(const float* __restrict__ feat)
{
    __shared__ float t[32][33];
    int n0 = blockIdx.x * 32, c0 = blockIdx.y * 32, b = blockIdx.z;
    int tx = threadIdx.x, ty = threadIdx.y;
#pragma unroll
    for (int j = 0; j < 32; j += 8)
        t[ty + j][tx] = feat[((size_t)b*64 + c0 + ty + j)*Nn + n0 + tx];
    __syncthreads();
#pragma unroll
    for (int j = 0; j < 32; j += 8)
        g_featT[((size_t)b*Nn + n0 + ty + j)*64 + c0 + tx] = t[tx][ty + j];
}

// ---------------- per-batch mean + max-norm ------------------------------
__global__ void reduce_coords(const float* __restrict__ coords)
{
    __shared__ float sm[1024];
    int b = blockIdx.x, tid = threadIdx.x;
    const float* px = coords + (size_t)b*3*Nn;
    const float* py = px + Nn;
    const float* pz = py + Nn;
    float sx = 0.f, sy = 0.f, sz = 0.f;
    for (int i = tid; i < Nn; i += 1024) { sx += px[i]; sy += py[i]; sz += pz[i]; }

    sm[tid] = sx; __syncthreads();
    for (int s = 512; s > 0; s >>= 1) { if (tid < s) sm[tid] += sm[tid + s]; __syncthreads(); }
    float mx = sm[0] * (1.f / Nn); __syncthreads();

    sm[tid] = sy; __syncthreads();
    for (int s = 512; s > 0; s >>= 1) { if (tid < s) sm[tid] += sm[tid + s]; __syncthreads(); }
    float my = sm[0] * (1.f / Nn); __syncthreads();

    sm[tid] = sz; __syncthreads();
    for (int s = 512; s > 0; s >>= 1) { if (tid < s) sm[tid] += sm[tid + s]; __syncthreads(); }
    float mz = sm[0] * (1.f / Nn); __syncthreads();

    float mm = 0.f;
    for (int i = tid; i < Nn; i += 1024) {
        float dx = px[i] - mx, dy = py[i] - my, dz = pz[i] - mz;
        mm = fmaxf(mm, dx*dx + dy*dy + dz*dz);
    }
    sm[tid] = mm; __syncthreads();
    for (int s = 512; s > 0; s >>= 1) { if (tid < s) sm[tid] = fmaxf(sm[tid], sm[tid + s]); __syncthreads(); }
    if (tid == 0) {
        g_mean[b*4 + 0] = mx; g_mean[b*4 + 1] = my; g_mean[b*4 + 2] = mz;
        g_scl[b] = (float)Rr / (2.f * sqrtf(sm[0]) * (1.f + 1e-6f));
    }
}

// ---------------- zero padded acc + cnt -----------------------------------
__global__ void zero_kernel()
{
    int i = blockIdx.x * 256 + threadIdx.x;   // 19652*256 = 5,030,912 float4 (exact)
    float4 z = make_float4(0.f, 0.f, 0.f, 0.f);
    reinterpret_cast<float4*>(g_accp)[i] = z;
    if (i < 78608) reinterpret_cast<float4*>(g_cnt)[i] = z;   // 314,432 floats
}

// ---------------- trilinear scatter into PADDED grid ----------------------
__global__ __launch_bounds__(256)
void scatter_kernel(const float* __restrict__ coords)
{
    int tid = threadIdx.x;
    int warp = tid >> 5, lane = tid & 31;
    int pid = blockIdx.x * 8 + warp;
    int b = pid >> 15, n = pid & (Nn - 1);

    float mx = g_mean[b*4+0], my = g_mean[b*4+1], mz = g_mean[b*4+2];
    float s  = g_scl[b];
    float cx = coords[((size_t)b*3 + 0)*Nn + n];
    float cy = coords[((size_t)b*3 + 1)*Nn + n];
    float cz = coords[((size_t)b*3 + 2)*Nn + n];
    float vx = fminf(fmaxf((cx - mx)*s + 16.f, 0.f), 31.f);
    float vy = fminf(fmaxf((cy - my)*s + 16.f, 0.f), 31.f);
    float vz = fminf(fmaxf((cz - mz)*s + 16.f, 0.f), 31.f);
    float fx = floorf(vx), fy = floorf(vy), fz = floorf(vz);
    int ix = (int)fx, iy = (int)fy, iz = (int)fz;
    float frx = vx - fx, fry = vy - fy, frz = vz - fz;

    float f0 = g_featT[(size_t)pid*64 + lane];
    float f1 = g_featT[(size_t)pid*64 + 32 + lane];

#pragma unroll
    for (int k = 0; k < 8; ++k) {
        int dx = k >> 2, dy = (k >> 1) & 1, dz = k & 1;
        int xi = min(ix + dx, 31), yi = min(iy + dy, 31), zi = min(iz + dz, 31);
        float w = (dx ? frx : 1.f - frx) * (dy ? fry : 1.f - fry) * (dz ? frz : 1.f - frz);
        size_t vb = (size_t)b*RP3 + (size_t)((xi+1)*34 + (yi+1))*34 + (zi+1);
        float* ap = g_accp + vb*64;
        atomicAdd(ap + lane,      w * f0);
        atomicAdd(ap + lane + 32, w * f1);
        if (lane == 0) atomicAdd(&g_cnt[vb], w);
    }
}

// ---------------- normalize + convert to bf16 hi/lo (whole padded grid) ---
__global__ void norm_convert()
{
    int idx = blockIdx.x * 256 + threadIdx.x;   // 5,030,912 float4 (exact)
    int row = idx >> 4;
    float c = g_cnt[row];
    float r = 1.f / fmaxf(c, 1e-8f);
    float4 f = reinterpret_cast<const float4*>(g_accp)[idx];
    float v0 = f.x*r, v1 = f.y*r, v2 = f.z*r, v3 = f.w*r;
    uint32_t h0 = bfpack(v0, v1), h1 = bfpack(v2, v3);
    float a0 = __uint_as_float(h0 << 16), a1 = __uint_as_float(h0 & 0xFFFF0000u);
    float a2 = __uint_as_float(h1 << 16), a3 = __uint_as_float(h1 & 0xFFFF0000u);
    uint32_t l0 = bfpack(v0 - a0, v1 - a1), l1 = bfpack(v2 - a2, v3 - a3);
    reinterpret_cast<uint2*>(g_vhi)[idx] = make_uint2(h0, h1);
    reinterpret_cast<uint2*>(g_vlo)[idx] = make_uint2(l0, l1);
}

// ---------------- mma.sync implicit-GEMM 3x3x3 conv ------------------------
// Block: 256 threads = 8 warps. Tile: 128 voxels (4y x 32z) x 64 co.
// Warp tile: 32m x 32n via 2x4 grid of m16n8k16 bf16 mma, fp32 acc.
// 27 taps x (hh + hl + lh) hi/lo passes, cp.async double-buffered SMEM.
#define SMEM_BUF 49152
#define OFF_ALO 16384
#define OFF_WHI 32768
#define OFF_WLO 40960
#define SMEM_DYN 98304

__device__ __forceinline__ void load_tap(
    uint32_t bufb, const __nv_bfloat16* __restrict__ inHi, const __nv_bfloat16* __restrict__ inLo,
    const __nv_bfloat16* __restrict__ wHi, const __nv_bfloat16* __restrict__ wLo,
    int b, int x, int y0, int tid, int tap)
{
    int dx = tap / 9, rr = tap - dx*9, dy = rr / 3, dz = rr - dy*3;
    // A: 128 voxel rows x 128B, hi (threads 0-127) and lo (threads 128-255)
    int m = tid & 127;
    size_t p = (size_t)b*RP3 + ((size_t)(x + dx)*34 + (y0 + (m >> 5) + dy))*34 + (m & 31) + dz;
    const char* asrc = (const char*)(((tid < 128) ? inHi : inLo) + p*64);
    uint32_t adst = bufb + ((tid < 128) ? 0u : (uint32_t)OFF_ALO);
    uint32_t aro = (uint32_t)m * 128;
#pragma unroll
    for (int j = 0; j < 8; ++j)
        cp_async16(adst + SWZ(aro + j*16), asrc + j*16);
    // W: 64 rows hi + 64 rows lo, x 128B; each thread loads half a row (64B)
    int wr = tid >> 1, h = tid & 1;
    const char* wsrc = (const char*)(((wr < 64) ? (wHi + tap*4096 + wr*64)
                                                : (wLo + tap*4096 + (wr - 64)*64))) + h*64;
    uint32_t wdst = bufb + ((wr < 64) ? (uint32_t)OFF_WHI : (uint32_t)OFF_WLO);
    uint32_t wro = (uint32_t)(wr & 63) * 128 + (uint32_t)h * 64;
#pragma unroll
    for (int j = 0; j < 4; ++j)
        cp_async16(wdst + SWZ(wro + j*16), wsrc + j*16);
}

__global__ void __launch_bounds__(256, 2)
conv_mma(const __nv_bfloat16* __restrict__ inHi, const __nv_bfloat16* __restrict__ inLo,
         const __nv_bfloat16* __restrict__ wHi,  const __nv_bfloat16* __restrict__ wLo,
         const float* __restrict__ sc, const float* __restrict__ bi,
         __nv_bfloat16* __restrict__ outHi, __nv_bfloat16* __restrict__ outLo,
         float* __restrict__ outF, int mode)
{
    extern __shared__ char smem[];
    __shared__ float s_sc[64], s_bi[64];
    const uint32_t sbase = smem_u32(smem);
    const int tid = threadIdx.x;
    const int warp = tid >> 5, lane = tid & 31;
    const int b = blockIdx.z, x = blockIdx.y, y0 = blockIdx.x * 4;
    if (tid < 64) { s_sc[tid] = sc[tid]; s_bi[tid] = bi[tid]; }

    const int mrow = warp & 3;       // 32-voxel chunk
    const int ncol = warp >> 2;      // 32-co chunk
    const int arow = lane & 15;
    const int acolo = (lane & 16) ? 16 : 0;
    const int brow = (lane & 7) + ((lane & 16) >> 1);
    const int bcolo = (lane & 8) ? 16 : 0;

    float acc[2][4][4];
#pragma unroll
    for (int i = 0; i < 2; ++i)
#pragma unroll
        for (int j = 0; j < 4; ++j)
#pragma unroll
            for (int q = 0; q < 4; ++q) acc[i][j][q] = 0.f;

    load_tap(sbase, inHi, inLo, wHi, wLo, b, x, y0, tid, 0);
    asm volatile("cp.async.commit_group;" ::: "memory");

    for (int t = 0; t < 27; ++t) {
        int cb = t & 1;
        if (t + 1 < 27) {
            load_tap(sbase + (cb ^ 1)*SMEM_BUF, inHi, inLo, wHi, wLo, b, x, y0, tid, t + 1);
            asm volatile("cp.async.commit_group;" ::: "memory");
            asm volatile("cp.async.wait_group 1;" ::: "memory");
        } else {
            asm volatile("cp.async.wait_group 0;" ::: "memory");
        }
        __syncthreads();

        uint32_t aH = sbase + cb*SMEM_BUF;
        uint32_t aL = aH + OFF_ALO;
        uint32_t wH = aH + OFF_WHI;
        uint32_t wL = aH + OFF_WLO;
#pragma unroll
        for (int k = 0; k < 4; ++k) {
            uint32_t fAh[2][4], fAl[2][4], fWh[2][4], fWl[2][4];
#pragma unroll
            for (int mi = 0; mi < 2; ++mi) {
                uint32_t off = (uint32_t)((mrow*32 + mi*16 + arow) << 7) + k*32 + acolo;
                ldsm4(fAh[mi], aH + SWZ(off));
                ldsm4(fAl[mi], aL + SWZ(off));
            }
#pragma unroll
            for (int ni = 0; ni < 2; ++ni) {
                uint32_t off = (uint32_t)((ncol*32 + ni*16 + brow) << 7) + k*32 + bcolo;
                ldsm4(fWh[ni], wH + SWZ(off));
                ldsm4(fWl[ni], wL + SWZ(off));
            }
#pragma unroll
            for (int mi = 0; mi < 2; ++mi)
#pragma unroll
                for (int ni = 0; ni < 2; ++ni) {
                    mma16816(acc[mi][2*ni+0], fAh[mi], fWh[ni][0], fWh[ni][1]);
                    mma16816(acc[mi][2*ni+1], fAh[mi], fWh[ni][2], fWh[ni][3]);
                    mma16816(acc[mi][2*ni+0], fAh[mi], fWl[ni][0], fWl[ni][1]);
                    mma16816(acc[mi][2*ni+1], fAh[mi], fWl[ni][2], fWl[ni][3]);
                    mma16816(acc[mi][2*ni+0], fAl[mi], fWh[ni][0], fWh[ni][1]);
                    mma16816(acc[mi][2*ni+1], fAl[mi], fWh[ni][2], fWh[ni][3]);
                }
        }
        __syncthreads();
    }

    // epilogue: BN fold + LeakyReLU(0.1)
    const int g = lane >> 2, tg = lane & 3;
#pragma unroll
    for (int mi = 0; mi < 2; ++mi) {
#pragma unroll
        for (int rs = 0; rs < 2; ++rs) {
            int m = mrow*32 + mi*16 + rs*8 + g;
            int yv = y0 + (m >> 5), zv = m & 31;
            if (mode == 0) {
                size_t p = (size_t)b*RP3 + ((size_t)(x + 1)*34 + (yv + 1))*34 + (zv + 1);
                __nv_bfloat16* oh = outHi + p*64;
                __nv_bfloat16* ol = outLo + p*64;
#pragma unroll
                for (int nj = 0; nj < 4; ++nj) {
                    int c = ncol*32 + nj*8 + tg*2;
                    float v0 = acc[mi][nj][rs*2+0]*s_sc[c]   + s_bi[c];
                    float v1 = acc[mi][nj][rs*2+1]*s_sc[c+1] + s_bi[c+1];
                    v0 = v0 > 0.f ? v0 : 0.1f*v0;
                    v1 = v1 > 0.f ? v1 : 0.1f*v1;
                    uint32_t h = bfpack(v0, v1);
                    float h0 = __uint_as_float(h << 16);
                    float h1 = __uint_as_float(h & 0xFFFF0000u);
                    uint32_t l = bfpack(v0 - h0, v1 - h1);
                    *reinterpret_cast<uint32_t*>(oh + c) = h;
                    *reinterpret_cast<uint32_t*>(ol + c) = l;
                }
            } else {
                float* of = outF + ((size_t)b*R3v + (size_t)(x*32 + yv)*32 + zv)*64;
#pragma unroll
                for (int nj = 0; nj < 4; ++nj) {
                    int c = ncol*32 + nj*8 + tg*2;
                    float v0 = acc[mi][nj][rs*2+0]*s_sc[c]   + s_bi[c];
                    float v1 = acc[mi][nj][rs*2+1]*s_sc[c+1] + s_bi[c+1];
                    v0 = v0 > 0.f ? v0 : 0.1f*v0;
                    v1 = v1 > 0.f ? v1 : 0.1f*v1;
                    *reinterpret_cast<float2*>(of + c) = make_float2(v0, v1);
                }
            }
        }
    }
}

// ---------------- devoxelize + point-MLP branch + output -------------------
__global__ __launch_bounds__(256)
void devox_kernel(const float* __restrict__ coords, float* __restrict__ out)
{
    __shared__ float s_mlpT[64*64];
    __shared__ float s_out[64][9];
    int tid = threadIdx.x;
#pragma unroll 1
    for (int e = tid; e < 4096; e += 256) s_mlpT[e] = g_mlpT[e];

    int warp = tid >> 5, lane = tid & 31;
    int pid0 = blockIdx.x * 8;
    int pid = pid0 + warp;
    int b = pid >> 15, n = pid & (Nn - 1);
    __syncthreads();

    float mx = g_mean[b*4+0], my = g_mean[b*4+1], mz = g_mean[b*4+2];
    float s  = g_scl[b];
    float cx = coords[((size_t)b*3 + 0)*Nn + n];
    float cy = coords[((size_t)b*3 + 1)*Nn + n];
    float cz = coords[((size_t)b*3 + 2)*Nn + n];
    float vx = fminf(fmaxf((cx - mx)*s + 16.f, 0.f), 31.f);
    float vy = fminf(fmaxf((cy - my)*s + 16.f, 0.f), 31.f);
    float vz = fminf(fmaxf((cz - mz)*s + 16.f, 0.f), 31.f);
    float fx = floorf(vx), fy = floorf(vy), fz = floorf(vz);
    int ix = (int)fx, iy = (int)fy, iz = (int)fz;
    float frx = vx - fx, fry = vy - fy, frz = vz - fz;

    float f0 = g_featT[(size_t)pid*64 + lane];
    float f1 = g_featT[(size_t)pid*64 + 32 + lane];
    float p0 = 0.f, p1 = 0.f;
#pragma unroll 1
    for (int c = 0; c < 64; ++c) {
        float fc = __shfl_sync(0xffffffffu, (c < 32) ? f0 : f1, c & 31);
        p0 = fmaf(s_mlpT[c*64 + lane],      fc, p0);
        p1 = fmaf(s_mlpT[c*64 + 32 + lane], fc, p1);
    }

    float d0 = 0.f, d1 = 0.f;
#pragma unroll
    for (int k = 0; k < 8; ++k) {
        int dx = k >> 2, dy = (k >> 1) & 1, dz = k & 1;
        int xi = min(ix + dx, 31), yi = min(iy + dy, 31), zi = min(iz + dz, 31);
        float w = (dx ? frx : 1.f - frx) * (dy ? fry : 1.f - fry) * (dz ? frz : 1.f - frz);
        const float* gp = g_c2 + ((size_t)b*R3v + ((xi*32 + yi)*32 + zi))*64;
        d0 = fmaf(w, gp[lane],      d0);
        d1 = fmaf(w, gp[lane + 32], d1);
    }
    p0 = fmaxf(fmaf(p0, g_sp[lane],      g_bp[lane]),      0.f);
    p1 = fmaxf(fmaf(p1, g_sp[lane + 32], g_bp[lane + 32]), 0.f);
    s_out[lane][warp]      = d0 + p0;
    s_out[lane + 32][warp] = d1 + p1;
    __syncthreads();

    int bb = pid0 >> 15;
    int n0 = pid0 & (Nn - 1);
#pragma unroll
    for (int e = tid; e < 512; e += 256) {
        int o = e >> 3, pi = e & 7;
        out[((size_t)bb*64 + o)*Nn + n0 + pi] = s_out[o][pi];
    }
}

// ---------------- launch ---------------------------------------------------
extern "C" void kernel_launch(void* const* d_in, const int* in_sizes, int n_in,
                              void* d_out, int out_size)
{
    const float* features = (const float*)d_in[0];
    const float* coords   = (const float*)d_in[1];
    const float* conv1_w  = (const float*)d_in[2];
    const float* conv1_b  = (const float*)d_in[3];
    const float* bn1_g    = (const float*)d_in[4];
    const float* bn1_b    = (const float*)d_in[5];
    const float* bn1_m    = (const float*)d_in[6];
    const float* bn1_v    = (const float*)d_in[7];
    const float* conv2_w  = (const float*)d_in[8];
    const float* conv2_b  = (const float*)d_in[9];
    const float* bn2_g    = (const float*)d_in[10];
    const float* bn2_b    = (const float*)d_in[11];
    const float* bn2_m    = (const float*)d_in[12];
    const float* bn2_v    = (const float*)d_in[13];
    const float* mlp_w    = (const float*)d_in[14];
    const float* mlp_b    = (const float*)d_in[15];
    const float* bnp_g    = (const float*)d_in[16];
    const float* bnp_b    = (const float*)d_in[17];
    const float* bnp_m    = (const float*)d_in[18];
    const float* bnp_v    = (const float*)d_in[19];
    float* out = (float*)d_out;

    void *p_vhi, *p_vlo, *p_1hi, *p_1lo, *p_c2;
    void *p_w1hi, *p_w1lo, *p_w2hi, *p_w2lo;
    void *p_s1, *p_b1, *p_s2, *p_b2;
    cudaGetSymbolAddress(&p_vhi,  g_vhi);
    cudaGetSymbolAddress(&p_vlo,  g_vlo);
    cudaGetSymbolAddress(&p_1hi,  g_1hi);
    cudaGetSymbolAddress(&p_1lo,  g_1lo);
    cudaGetSymbolAddress(&p_c2,   g_c2);
    cudaGetSymbolAddress(&p_w1hi, g_w1hi);
    cudaGetSymbolAddress(&p_w1lo, g_w1lo);
    cudaGetSymbolAddress(&p_w2hi, g_w2hi);
    cudaGetSymbolAddress(&p_w2lo, g_w2lo);
    cudaGetSymbolAddress(&p_s1,   g_s1);
    cudaGetSymbolAddress(&p_b1,   g_b1);
    cudaGetSymbolAddress(&p_s2,   g_s2);
    cudaGetSymbolAddress(&p_b2,   g_b2);

    cudaFuncSetAttribute(conv_mma, cudaFuncAttributeMaxDynamicSharedMemorySize, SMEM_DYN);

    prep_params<<<1, 64>>>(conv1_b, bn1_g, bn1_b, bn1_m, bn1_v,
                           conv2_b, bn2_g, bn2_b, bn2_m, bn2_v,
                           mlp_w, mlp_b, bnp_g, bnp_b, bnp_m, bnp_v);
    prep_weights<<<864, 256>>>(conv1_w, conv2_w);
    transpose_feat<<<dim3(Nn/32, 2, Bz), dim3(32, 8)>>>(features);
    reduce_coords<<<Bz, 1024>>>(coords);
    zero_kernel<<<19652, 256>>>();
    scatter_kernel<<<(Bz*Nn)/8, 256>>>(coords);
    norm_convert<<<19652, 256>>>();
    conv_mma<<<dim3(8, 32, Bz), 256, SMEM_DYN>>>(
        (const __nv_bfloat16*)p_vhi, (const __nv_bfloat16*)p_vlo,
        (const __nv_bfloat16*)p_w1hi, (const __nv_bfloat16*)p_w1lo,
        (const float*)p_s1, (const float*)p_b1,
        (__nv_bfloat16*)p_1hi, (__nv_bfloat16*)p_1lo, nullptr, 0);
    conv_mma<<<dim3(8, 32, Bz), 256, SMEM_DYN>>>(
        (const __nv_bfloat16*)p_1hi, (const __nv_bfloat16*)p_1lo,
        (const __nv_bfloat16*)p_w2hi, (const __nv_bfloat16*)p_w2lo,
        (const float*)p_s2, (const float*)p_b2,
        nullptr, nullptr, (float*)p_c2, 1);
    devox_kernel<<<(Bz*Nn)/8, 256>>>(coords, out);
    cudaMemcpyAsync(out + (size_t)Bz*64*Nn, coords,
                    (size_t)Bz*3*Nn*sizeof(float), cudaMemcpyDeviceToDevice);
}

// round 17
// speedup vs baseline: 1.7685x; 1.0005x over previous
#include <cuda_runtime.h>
#include <cuda_bf16.h>
#include <math.h>
#include <stdint.h>

#define Bz 8
#define Nn 32768
#define Rr 32
#define R3v (Rr*Rr*Rr)
#define RP 34
#define RP3 (RP*RP*RP)   // 39304 padded rows per batch

// ---------------- device scratch (no allocations allowed) ----------------
__device__ __align__(16) float g_accp[(size_t)Bz*RP3*64];  // padded voxel accum fp32
__device__ __align__(16) float g_cnt[Bz*RP3];
__device__ __align__(16) float g_c2 [(size_t)Bz*R3v*64];   // conv2 out fp32 (channels-last)
__device__ __align__(16) float g_featT[(size_t)Bz*Nn*64];  // features [b][n][c]
__device__ __align__(16) __nv_bfloat16 g_vhi[(size_t)Bz*RP3*64];  // conv1 input hi
__device__ __align__(16) __nv_bfloat16 g_vlo[(size_t)Bz*RP3*64];  // conv1 input lo
__device__ __align__(16) __nv_bfloat16 g_1hi[(size_t)Bz*RP3*64];  // conv2 input hi
__device__ __align__(16) __nv_bfloat16 g_1lo[(size_t)Bz*RP3*64];  // conv2 input lo
__device__ __align__(16) __nv_bfloat16 g_w1hi[27*64*64], g_w1lo[27*64*64]; // [t][co][ci]
__device__ __align__(16) __nv_bfloat16 g_w2hi[27*64*64], g_w2lo[27*64*64];
__device__ __align__(16) float g_mlpT[64*64];              // [c][o]
__device__ float g_s1[64], g_b1[64], g_s2[64], g_b2[64], g_sp[64], g_bp[64];
__device__ float g_mean[Bz*4];
__device__ float g_scl[Bz];

// ---------------- PTX helpers ---------------------------------------------
static __device__ __forceinline__ uint32_t smem_u32(const void* p) {
    uint32_t a;
    asm("{ .reg .u64 t; cvta.to.shared.u64 t, %1; cvt.u32.u64 %0, t; }" : "=r"(a) : "l"(p));
    return a;
}
#define SWZ(o) ((o) ^ (((o) >> 3) & 0x70))
__device__ __forceinline__ void cp_async16(uint32_t dst, const void* src) {
    asm volatile("cp.async.cg.shared.global [%0], [%1], 16;" :: "r"(dst), "l"(src));
}
__device__ __forceinline__ void ldsm4(uint32_t* r, uint32_t addr) {
    asm volatile("ldmatrix.sync.aligned.m8n8.x4.shared.b16 {%0,%1,%2,%3}, [%4];"
        : "=r"(r[0]), "=r"(r[1]), "=r"(r[2]), "=r"(r[3]) : "r"(addr));
}
__device__ __forceinline__ void mma16816(float* d, const uint32_t* a, uint32_t b0, uint32_t b1) {
    asm volatile("mma.sync.aligned.m16n8k16.row.col.f32.bf16.bf16.f32 "
        "{%0,%1,%2,%3}, {%4,%5,%6,%7}, {%8,%9}, {%0,%1,%2,%3};"
        : "+f"(d[0]), "+f"(d[1]), "+f"(d[2]), "+f"(d[3])
        : "r"(a[0]), "r"(a[1]), "r"(a[2]), "r"(a[3]), "r"(b0), "r"(b1));
}
__device__ __forceinline__ uint32_t bfpack(float lo, float hi) {
    uint32_t r;
    asm("cvt.rn.bf16x2.f32 %0, %1, %2;" : "=r"(r) : "f"(hi), "f"(lo));
    return r;
}

// ---------------- prep: fold BN into scale/bias, transpose mlp -----------
__global__ void prep_params(
    const float* __restrict__ conv1_b, const float* __restrict__ bn1_g, const float* __restrict__ bn1_b,
    const float* __restrict__ bn1_m,  const float* __restrict__ bn1_v,
    const float* __restrict__ conv2_b, const float* __restrict__ bn2_g, const float* __restrict__ bn2_b,
    const float* __restrict__ bn2_m,  const float* __restrict__ bn2_v,
    const float* __restrict__ mlp_w,  const float* __restrict__ mlp_b,
    const float* __restrict__ bnp_g,  const float* __restrict__ bnp_b,
    const float* __restrict__ bnp_m,  const float* __restrict__ bnp_v)
{
    int c = threadIdx.x;
    if (c < 64) {
        float s1 = bn1_g[c] * rsqrtf(bn1_v[c] + 1e-4f);
        g_s1[c] = s1;  g_b1[c] = (conv1_b[c] - bn1_m[c]) * s1 + bn1_b[c];
        float s2 = bn2_g[c] * rsqrtf(bn2_v[c] + 1e-4f);
        g_s2[c] = s2;  g_b2[c] = (conv2_b[c] - bn2_m[c]) * s2 + bn2_b[c];
        float sp = bnp_g[c] * rsqrtf(bnp_v[c] + 1e-4f);
        g_sp[c] = sp;  g_bp[c] = (mlp_b[c] - bnp_m[c]) * sp + bnp_b[c];
        for (int o = 0; o < 64; ++o) g_mlpT[c*64 + o] = mlp_w[o*64 + c];
    }
}

// ---------------- weights [co][ci][27] -> bf16 hi/lo [t][co][ci] ----------
__global__ void prep_weights(const float* __restrict__ w1, const float* __restrict__ w2)
{
    int e = blockIdx.x * 256 + threadIdx.x;   // 221184 total
    const float* src = (e < 110592) ? w1 : w2;
    int o = (e < 110592) ? e : e - 110592;
    int ci = o & 63, co = (o >> 6) & 63, t = o >> 12;
    float v = src[(co*64 + ci)*27 + t];
    __nv_bfloat16 h = __float2bfloat16_rn(v);
    __nv_bfloat16 l = __float2bfloat16_rn(v - __bfloat162float(h));
    int dst = t*4096 + co*64 + ci;
    if (e < 110592) { g_w1hi[dst] = h; g_w1lo[dst] = l; }
    else            { g_w2hi[dst] = h; g_w2lo[dst] = l; }
}

// ---------------- features [b][c][n] -> [b][n][c] ------------------------
__global__ void transpose_feat(const float* __restrict__ feat)
{
    __shared__ float t[32][33];
    int n0 = blockIdx.x * 32, c0 = blockIdx.y * 32, b = blockIdx.z;
    int tx = threadIdx.x, ty = threadIdx.y;
#pragma unroll
    for (int j = 0; j < 32; j += 8)
        t[ty + j][tx] = feat[((size_t)b*64 + c0 + ty + j)*Nn + n0 + tx];
    __syncthreads();
#pragma unroll
    for (int j = 0; j < 32; j += 8)
        g_featT[((size_t)b*Nn + n0 + ty + j)*64 + c0 + tx] = t[tx][ty + j];
}

// ---------------- per-batch mean + max-norm ------------------------------
__global__ void reduce_coords(const float* __restrict__ coords)
{
    __shared__ float sm[1024];
    int b = blockIdx.x, tid = threadIdx.x;
    const float* px = coords + (size_t)b*3*Nn;
    const float* py = px + Nn;
    const float* pz = py + Nn;
    float sx = 0.f, sy = 0.f, sz = 0.f;
    for (int i = tid; i < Nn; i += 1024) { sx += px[i]; sy += py[i]; sz += pz[i]; }

    sm[tid] = sx; __syncthreads();
    for (int s = 512; s > 0; s >>= 1) { if (tid < s) sm[tid] += sm[tid + s]; __syncthreads(); }
    float mx = sm[0] * (1.f / Nn); __syncthreads();

    sm[tid] = sy; __syncthreads();
    for (int s = 512; s > 0; s >>= 1) { if (tid < s) sm[tid] += sm[tid + s]; __syncthreads(); }
    float my = sm[0] * (1.f / Nn); __syncthreads();

    sm[tid] = sz; __syncthreads();
    for (int s = 512; s > 0; s >>= 1) { if (tid < s) sm[tid] += sm[tid + s]; __syncthreads(); }
    float mz = sm[0] * (1.f / Nn); __syncthreads();

    float mm = 0.f;
    for (int i = tid; i < Nn; i += 1024) {
        float dx = px[i] - mx, dy = py[i] - my, dz = pz[i] - mz;
        mm = fmaxf(mm, dx*dx + dy*dy + dz*dz);
    }
    sm[tid] = mm; __syncthreads();
    for (int s = 512; s > 0; s >>= 1) { if (tid < s) sm[tid] = fmaxf(sm[tid], sm[tid + s]); __syncthreads(); }
    if (tid == 0) {
        g_mean[b*4 + 0] = mx; g_mean[b*4 + 1] = my; g_mean[b*4 + 2] = mz;
        g_scl[b] = (float)Rr / (2.f * sqrtf(sm[0]) * (1.f + 1e-6f));
    }
}

// ---------------- zero padded acc + cnt -----------------------------------
__global__ void zero_kernel()
{
    int i = blockIdx.x * 256 + threadIdx.x;   // 19652*256 = 5,030,912 float4 (exact)
    float4 z = make_float4(0.f, 0.f, 0.f, 0.f);
    reinterpret_cast<float4*>(g_accp)[i] = z;
    if (i < 78608) reinterpret_cast<float4*>(g_cnt)[i] = z;   // 314,432 floats
}

// ---------------- trilinear scatter into PADDED grid ----------------------
__global__ __launch_bounds__(256)
void scatter_kernel(const float* __restrict__ coords)
{
    int tid = threadIdx.x;
    int warp = tid >> 5, lane = tid & 31;
    int pid = blockIdx.x * 8 + warp;
    int b = pid >> 15, n = pid & (Nn - 1);

    float mx = g_mean[b*4+0], my = g_mean[b*4+1], mz = g_mean[b*4+2];
    float s  = g_scl[b];
    float cx = coords[((size_t)b*3 + 0)*Nn + n];
    float cy = coords[((size_t)b*3 + 1)*Nn + n];
    float cz = coords[((size_t)b*3 + 2)*Nn + n];
    float vx = fminf(fmaxf((cx - mx)*s + 16.f, 0.f), 31.f);
    float vy = fminf(fmaxf((cy - my)*s + 16.f, 0.f), 31.f);
    float vz = fminf(fmaxf((cz - mz)*s + 16.f, 0.f), 31.f);
    float fx = floorf(vx), fy = floorf(vy), fz = floorf(vz);
    int ix = (int)fx, iy = (int)fy, iz = (int)fz;
    float frx = vx - fx, fry = vy - fy, frz = vz - fz;

    float f0 = g_featT[(size_t)pid*64 + lane];
    float f1 = g_featT[(size_t)pid*64 + 32 + lane];

#pragma unroll
    for (int k = 0; k < 8; ++k) {
        int dx = k >> 2, dy = (k >> 1) & 1, dz = k & 1;
        int xi = min(ix + dx, 31), yi = min(iy + dy, 31), zi = min(iz + dz, 31);
        float w = (dx ? frx : 1.f - frx) * (dy ? fry : 1.f - fry) * (dz ? frz : 1.f - frz);
        size_t vb = (size_t)b*RP3 + (size_t)((xi+1)*34 + (yi+1))*34 + (zi+1);
        float* ap = g_accp + vb*64;
        atomicAdd(ap + lane,      w * f0);
        atomicAdd(ap + lane + 32, w * f1);
        if (lane == 0) atomicAdd(&g_cnt[vb], w);
    }
}

// ---------------- normalize + convert to bf16 hi/lo (whole padded grid) ---
__global__ void norm_convert()
{
    int idx = blockIdx.x * 256 + threadIdx.x;   // 5,030,912 float4 (exact)
    int row = idx >> 4;
    float c = g_cnt[row];
    float r = 1.f / fmaxf(c, 1e-8f);
    float4 f = reinterpret_cast<const float4*>(g_accp)[idx];
    float v0 = f.x*r, v1 = f.y*r, v2 = f.z*r, v3 = f.w*r;
    uint32_t h0 = bfpack(v0, v1), h1 = bfpack(v2, v3);
    float a0 = __uint_as_float(h0 << 16), a1 = __uint_as_float(h0 & 0xFFFF0000u);
    float a2 = __uint_as_float(h1 << 16), a3 = __uint_as_float(h1 & 0xFFFF0000u);
    uint32_t l0 = bfpack(v0 - a0, v1 - a1), l1 = bfpack(v2 - a2, v3 - a3);
    reinterpret_cast<uint2*>(g_vhi)[idx] = make_uint2(h0, h1);
    reinterpret_cast<uint2*>(g_vlo)[idx] = make_uint2(l0, l1);
}

// ---------------- mma.sync implicit-GEMM 3x3x3 conv ------------------------
// Block: 256 threads = 8 warps. Tile: 128 voxels (4y x 32z) x 64 co.
// Warp tile: 32m x 32n via 2x4 grid of m16n8k16 bf16 mma, fp32 acc.
// 27 taps x (hh + hl + lh) hi/lo passes, cp.async double-buffered SMEM.
#define SMEM_BUF 49152
#define OFF_ALO 16384
#define OFF_WHI 32768
#define OFF_WLO 40960
#define SMEM_DYN 98304

__device__ __forceinline__ void load_tap(
    uint32_t bufb, const __nv_bfloat16* __restrict__ inHi, const __nv_bfloat16* __restrict__ inLo,
    const __nv_bfloat16* __restrict__ wHi, const __nv_bfloat16* __restrict__ wLo,
    int b, int x, int y0, int tid, int tap)
{
    int dx = tap / 9, rr = tap - dx*9, dy = rr / 3, dz = rr - dy*3;
    // A: 128 voxel rows x 128B, hi (threads 0-127) and lo (threads 128-255)
    int m = tid & 127;
    size_t p = (size_t)b*RP3 + ((size_t)(x + dx)*34 + (y0 + (m >> 5) + dy))*34 + (m & 31) + dz;
    const char* asrc = (const char*)(((tid < 128) ? inHi : inLo) + p*64);
    uint32_t adst = bufb + ((tid < 128) ? 0u : (uint32_t)OFF_ALO);
    uint32_t aro = (uint32_t)m * 128;
#pragma unroll
    for (int j = 0; j < 8; ++j)
        cp_async16(adst + SWZ(aro + j*16), asrc + j*16);
    // W: 64 rows hi + 64 rows lo, x 128B; each thread loads half a row (64B)
    int wr = tid >> 1, h = tid & 1;
    const char* wsrc = (const char*)(((wr < 64) ? (wHi + tap*4096 + wr*64)
                                                : (wLo + tap*4096 + (wr - 64)*64))) + h*64;
    uint32_t wdst = bufb + ((wr < 64) ? (uint32_t)OFF_WHI : (uint32_t)OFF_WLO);
    uint32_t wro = (uint32_t)(wr & 63) * 128 + (uint32_t)h * 64;
#pragma unroll
    for (int j = 0; j < 4; ++j)
        cp_async16(wdst + SWZ(wro + j*16), wsrc + j*16);
}

__global__ void __launch_bounds__(256, 2)
conv_mma(const __nv_bfloat16* __restrict__ inHi, const __nv_bfloat16* __restrict__ inLo,
         const __nv_bfloat16* __restrict__ wHi,  const __nv_bfloat16* __restrict__ wLo,
         const float* __restrict__ sc, const float* __restrict__ bi,
         __nv_bfloat16* __restrict__ outHi, __nv_bfloat16* __restrict__ outLo,
         float* __restrict__ outF, int mode)
{
    extern __shared__ char smem[];
    __shared__ float s_sc[64], s_bi[64];
    const uint32_t sbase = smem_u32(smem);
    const int tid = threadIdx.x;
    const int warp = tid >> 5, lane = tid & 31;
    const int b = blockIdx.z, x = blockIdx.y, y0 = blockIdx.x * 4;
    if (tid < 64) { s_sc[tid] = sc[tid]; s_bi[tid] = bi[tid]; }

    const int mrow = warp & 3;       // 32-voxel chunk
    const int ncol = warp >> 2;      // 32-co chunk
    const int arow = lane & 15;
    const int acolo = (lane & 16) ? 16 : 0;
    const int brow = (lane & 7) + ((lane & 16) >> 1);
    const int bcolo = (lane & 8) ? 16 : 0;

    float acc[2][4][4];
#pragma unroll
    for (int i = 0; i < 2; ++i)
#pragma unroll
        for (int j = 0; j < 4; ++j)
#pragma unroll
            for (int q = 0; q < 4; ++q) acc[i][j][q] = 0.f;

    load_tap(sbase, inHi, inLo, wHi, wLo, b, x, y0, tid, 0);
    asm volatile("cp.async.commit_group;" ::: "memory");

    for (int t = 0; t < 27; ++t) {
        int cb = t & 1;
        if (t + 1 < 27) {
            load_tap(sbase + (cb ^ 1)*SMEM_BUF, inHi, inLo, wHi, wLo, b, x, y0, tid, t + 1);
            asm volatile("cp.async.commit_group;" ::: "memory");
            asm volatile("cp.async.wait_group 1;" ::: "memory");
        } else {
            asm volatile("cp.async.wait_group 0;" ::: "memory");
        }
        __syncthreads();

        uint32_t aH = sbase + cb*SMEM_BUF;
        uint32_t aL = aH + OFF_ALO;
        uint32_t wH = aH + OFF_WHI;
        uint32_t wL = aH + OFF_WLO;
#pragma unroll
        for (int k = 0; k < 4; ++k) {
            uint32_t fAh[2][4], fAl[2][4], fWh[2][4], fWl[2][4];
#pragma unroll
            for (int mi = 0; mi < 2; ++mi) {
                uint32_t off = (uint32_t)((mrow*32 + mi*16 + arow) << 7) + k*32 + acolo;
                ldsm4(fAh[mi], aH + SWZ(off));
                ldsm4(fAl[mi], aL + SWZ(off));
            }
#pragma unroll
            for (int ni = 0; ni < 2; ++ni) {
                uint32_t off = (uint32_t)((ncol*32 + ni*16 + brow) << 7) + k*32 + bcolo;
                ldsm4(fWh[ni], wH + SWZ(off));
                ldsm4(fWl[ni], wL + SWZ(off));
            }
#pragma unroll
            for (int mi = 0; mi < 2; ++mi)
#pragma unroll
                for (int ni = 0; ni < 2; ++ni) {
                    mma16816(acc[mi][2*ni+0], fAh[mi], fWh[ni][0], fWh[ni][1]);
                    mma16816(acc[mi][2*ni+1], fAh[mi], fWh[ni][2], fWh[ni][3]);
                    mma16816(acc[mi][2*ni+0], fAh[mi], fWl[ni][0], fWl[ni][1]);
                    mma16816(acc[mi][2*ni+1], fAh[mi], fWl[ni][2], fWl[ni][3]);
                    mma16816(acc[mi][2*ni+0], fAl[mi], fWh[ni][0], fWh[ni][1]);
                    mma16816(acc[mi][2*ni+1], fAl[mi], fWh[ni][2], fWh[ni][3]);
                }
        }
        __syncthreads();
    }

    // epilogue: BN fold + LeakyReLU(0.1)
    const int g = lane >> 2, tg = lane & 3;
#pragma unroll
    for (int mi = 0; mi < 2; ++mi) {
#pragma unroll
        for (int rs = 0; rs < 2; ++rs) {
            int m = mrow*32 + mi*16 + rs*8 + g;
            int yv = y0 + (m >> 5), zv = m & 31;
            if (mode == 0) {
                size_t p = (size_t)b*RP3 + ((size_t)(x + 1)*34 + (yv + 1))*34 + (zv + 1);
                __nv_bfloat16* oh = outHi + p*64;
                __nv_bfloat16* ol = outLo + p*64;
#pragma unroll
                for (int nj = 0; nj < 4; ++nj) {
                    int c = ncol*32 + nj*8 + tg*2;
                    float v0 = acc[mi][nj][rs*2+0]*s_sc[c]   + s_bi[c];
                    float v1 = acc[mi][nj][rs*2+1]*s_sc[c+1] + s_bi[c+1];
                    v0 = v0 > 0.f ? v0 : 0.1f*v0;
                    v1 = v1 > 0.f ? v1 : 0.1f*v1;
                    uint32_t h = bfpack(v0, v1);
                    float h0 = __uint_as_float(h << 16);
                    float h1 = __uint_as_float(h & 0xFFFF0000u);
                    uint32_t l = bfpack(v0 - h0, v1 - h1);
                    *reinterpret_cast<uint32_t*>(oh + c) = h;
                    *reinterpret_cast<uint32_t*>(ol + c) = l;
                }
            } else {
                float* of = outF + ((size_t)b*R3v + (size_t)(x*32 + yv)*32 + zv)*64;
#pragma unroll
                for (int nj = 0; nj < 4; ++nj) {
                    int c = ncol*32 + nj*8 + tg*2;
                    float v0 = acc[mi][nj][rs*2+0]*s_sc[c]   + s_bi[c];
                    float v1 = acc[mi][nj][rs*2+1]*s_sc[c+1] + s_bi[c+1];
                    v0 = v0 > 0.f ? v0 : 0.1f*v0;
                    v1 = v1 > 0.f ? v1 : 0.1f*v1;
                    *reinterpret_cast<float2*>(of + c) = make_float2(v0, v1);
                }
            }
        }
    }
}

// ---------------- devoxelize + point-MLP branch + output -------------------
__global__ __launch_bounds__(256)
void devox_kernel(const float* __restrict__ coords, float* __restrict__ out)
{
    __shared__ float s_mlpT[64*64];
    __shared__ float s_out[64][9];
    int tid = threadIdx.x;
#pragma unroll 1
    for (int e = tid; e < 4096; e += 256) s_mlpT[e] = g_mlpT[e];

    int warp = tid >> 5, lane = tid & 31;
    int pid0 = blockIdx.x * 8;
    int pid = pid0 + warp;
    int b = pid >> 15, n = pid & (Nn - 1);
    __syncthreads();

    float mx = g_mean[b*4+0], my = g_mean[b*4+1], mz = g_mean[b*4+2];
    float s  = g_scl[b];
    float cx = coords[((size_t)b*3 + 0)*Nn + n];
    float cy = coords[((size_t)b*3 + 1)*Nn + n];
    float cz = coords[((size_t)b*3 + 2)*Nn + n];
    float vx = fminf(fmaxf((cx - mx)*s + 16.f, 0.f), 31.f);
    float vy = fminf(fmaxf((cy - my)*s + 16.f, 0.f), 31.f);
    float vz = fminf(fmaxf((cz - mz)*s + 16.f, 0.f), 31.f);
    float fx = floorf(vx), fy = floorf(vy), fz = floorf(vz);
    int ix = (int)fx, iy = (int)fy, iz = (int)fz;
    float frx = vx - fx, fry = vy - fy, frz = vz - fz;

    float f0 = g_featT[(size_t)pid*64 + lane];
    float f1 = g_featT[(size_t)pid*64 + 32 + lane];
    float p0 = 0.f, p1 = 0.f;
#pragma unroll 1
    for (int c = 0; c < 64; ++c) {
        float fc = __shfl_sync(0xffffffffu, (c < 32) ? f0 : f1, c & 31);
        p0 = fmaf(s_mlpT[c*64 + lane],      fc, p0);
        p1 = fmaf(s_mlpT[c*64 + 32 + lane], fc, p1);
    }

    float d0 = 0.f, d1 = 0.f;
#pragma unroll
    for (int k = 0; k < 8; ++k) {
        int dx = k >> 2, dy = (k >> 1) & 1, dz = k & 1;
        int xi = min(ix + dx, 31), yi = min(iy + dy, 31), zi = min(iz + dz, 31);
        float w = (dx ? frx : 1.f - frx) * (dy ? fry : 1.f - fry) * (dz ? frz : 1.f - frz);
        const float* gp = g_c2 + ((size_t)b*R3v + ((xi*32 + yi)*32 + zi))*64;
        d0 = fmaf(w, gp[lane],      d0);
        d1 = fmaf(w, gp[lane + 32], d1);
    }
    p0 = fmaxf(fmaf(p0, g_sp[lane],      g_bp[lane]),      0.f);
    p1 = fmaxf(fmaf(p1, g_sp[lane + 32], g_bp[lane + 32]), 0.f);
    s_out[lane][warp]      = d0 + p0;
    s_out[lane + 32][warp] = d1 + p1;
    __syncthreads();

    int bb = pid0 >> 15;
    int n0 = pid0 & (Nn - 1);
#pragma unroll
    for (int e = tid; e < 512; e += 256) {
        int o = e >> 3, pi = e & 7;
        out[((size_t)bb*64 + o)*Nn + n0 + pi] = s_out[o][pi];
    }
}

// ---------------- launch ---------------------------------------------------
extern "C" void kernel_launch(void* const* d_in, const int* in_sizes, int n_in,
                              void* d_out, int out_size)
{
    const float* features = (const float*)d_in[0];
    const float* coords   = (const float*)d_in[1];
    const float* conv1_w  = (const float*)d_in[2];
    const float* conv1_b  = (const float*)d_in[3];
    const float* bn1_g    = (const float*)d_in[4];
    const float* bn1_b    = (const float*)d_in[5];
    const float* bn1_m    = (const float*)d_in[6];
    const float* bn1_v    = (const float*)d_in[7];
    const float* conv2_w  = (const float*)d_in[8];
    const float* conv2_b  = (const float*)d_in[9];
    const float* bn2_g    = (const float*)d_in[10];
    const float* bn2_b    = (const float*)d_in[11];
    const float* bn2_m    = (const float*)d_in[12];
    const float* bn2_v    = (const float*)d_in[13];
    const float* mlp_w    = (const float*)d_in[14];
    const float* mlp_b    = (const float*)d_in[15];
    const float* bnp_g    = (const float*)d_in[16];
    const float* bnp_b    = (const float*)d_in[17];
    const float* bnp_m    = (const float*)d_in[18];
    const float* bnp_v    = (const float*)d_in[19];
    float* out = (float*)d_out;

    void *p_vhi, *p_vlo, *p_1hi, *p_1lo, *p_c2;
    void *p_w1hi, *p_w1lo, *p_w2hi, *p_w2lo;
    void *p_s1, *p_b1, *p_s2, *p_b2;
    cudaGetSymbolAddress(&p_vhi,  g_vhi);
    cudaGetSymbolAddress(&p_vlo,  g_vlo);
    cudaGetSymbolAddress(&p_1hi,  g_1hi);
    cudaGetSymbolAddress(&p_1lo,  g_1lo);
    cudaGetSymbolAddress(&p_c2,   g_c2);
    cudaGetSymbolAddress(&p_w1hi, g_w1hi);
    cudaGetSymbolAddress(&p_w1lo, g_w1lo);
    cudaGetSymbolAddress(&p_w2hi, g_w2hi);
    cudaGetSymbolAddress(&p_w2lo, g_w2lo);
    cudaGetSymbolAddress(&p_s1,   g_s1);
    cudaGetSymbolAddress(&p_b1,   g_b1);
    cudaGetSymbolAddress(&p_s2,   g_s2);
    cudaGetSymbolAddress(&p_b2,   g_b2);

    cudaFuncSetAttribute(conv_mma, cudaFuncAttributeMaxDynamicSharedMemorySize, SMEM_DYN);

    prep_params<<<1, 64>>>(conv1_b, bn1_g, bn1_b, bn1_m, bn1_v,
                           conv2_b, bn2_g, bn2_b, bn2_m, bn2_v,
                           mlp_w, mlp_b, bnp_g, bnp_b, bnp_m, bnp_v);
    prep_weights<<<864, 256>>>(conv1_w, conv2_w);
    transpose_feat<<<dim3(Nn/32, 2, Bz), dim3(32, 8)>>>(features);
    reduce_coords<<<Bz, 1024>>>(coords);
    zero_kernel<<<19652, 256>>>();
    scatter_kernel<<<(Bz*Nn)/8, 256>>>(coords);
    norm_convert<<<19652, 256>>>();
    conv_mma<<<dim3(8, 32, Bz), 256, SMEM_DYN>>>(
        (const __nv_bfloat16*)p_vhi, (const __nv_bfloat16*)p_vlo,
        (const __nv_bfloat16*)p_w1hi, (const __nv_bfloat16*)p_w1lo,
        (const float*)p_s1, (const float*)p_b1,
        (__nv_bfloat16*)p_1hi, (__nv_bfloat16*)p_1lo, nullptr, 0);
    conv_mma<<<dim3(8, 32, Bz), 256, SMEM_DYN>>>(
        (const __nv_bfloat16*)p_1hi, (const __nv_bfloat16*)p_1lo,
        (const __nv_bfloat16*)p_w2hi, (const __nv_bfloat16*)p_w2lo,
        (const float*)p_s2, (const float*)p_b2,
        nullptr, nullptr, (float*)p_c2, 1);
    devox_kernel<<<(Bz*Nn)/8, 256>>>(coords, out);
    cudaMemcpyAsync(out + (size_t)Bz*64*Nn, coords,
                    (size_t)Bz*3*Nn*sizeof(float), cudaMemcpyDeviceToDevice);
}